// round 5
// baseline (speedup 1.0000x reference)
#include <cuda_runtime.h>
#include <cstdint>

#define BATCH 16
#define MAXGT 64
#define NCLS 80
#define HWTOT 21824
#define NBLK 86                   // blocks per image: 64+16+4+1+1
#define TOTBLK (NBLK * BATCH)     // 1376

// Output layout (floats), concatenated in reference return order.
#define OFF_CLS_T 0ULL
#define OFF_CLS_M ((size_t)BATCH * HWTOT * NCLS)            // 27,934,720
#define OFF_NP    (OFF_CLS_M + (size_t)BATCH * HWTOT)       // 28,283,904
#define OFF_REG_T (OFF_NP + BATCH)                          // 28,283,920
#define OFF_REG_M (OFF_REG_T + (size_t)BATCH * HWTOT * 4)   // 29,680,656

__device__ float    d_np[BATCH];     // zero-init; reset by finalizer each replay
__device__ unsigned d_ticket = 0;    // completion ticket; reset each replay

// Shrunken/clipped region bounds exactly like reference _prop_box.
// __f*_rn intrinsics forbid FMA contraction (floor/ceil boundary safety).
static __device__ __forceinline__ void prop_bounds(
    float px1, float py1, float px2, float py2, float w, float h,
    float a, float ff,
    int& ox1, int& oy1, int& ox2, int& oy2)
{
    float n1 = floorf(__fadd_rn(px1, __fmul_rn(a, w)));
    float m1 = floorf(__fadd_rn(py1, __fmul_rn(a, h)));
    float n2 = ceilf (__fsub_rn(px2, __fmul_rn(a, w)));
    float m2 = ceilf (__fsub_rn(py2, __fmul_rn(a, h)));
    n2 = fminf(fmaxf(fmaxf(n2, n1 + 1.0f), 0.0f), ff);
    m2 = fminf(fmaxf(fmaxf(m2, m1 + 1.0f), 0.0f), ff);
    n1 = fminf(fmaxf(n1, 0.0f), ff - 1.0f);
    m1 = fminf(fmaxf(m1, 0.0f), ff - 1.0f);
    ox1 = (int)n1; oy1 = (int)m1; ox2 = (int)n2; oy2 = (int)m2;
}

__global__ void __launch_bounds__(256)
fsaf_all(const int* __restrict__ g_levels,
         const float* __restrict__ g_boxes,
         float* __restrict__ out)
{
    // Shared GT table, SoA.
    __shared__ int4   s_pos[MAXGT];
    __shared__ int4   s_ign[MAXGT];
    __shared__ int4   s_uni[MAXGT];
    __shared__ float4 s_box[MAXGT];
    __shared__ float  s_area[MAXGT];
    __shared__ int    s_lab[MAXGT];
    __shared__ int    s_n;
    __shared__ unsigned s_tick;

    const int img = blockIdx.y;
    const int bx  = blockIdx.x;

    int lvl, tile;
    if      (bx < 64) { lvl = 0; tile = bx;      }
    else if (bx < 80) { lvl = 1; tile = bx - 64; }
    else if (bx < 84) { lvl = 2; tile = bx - 80; }
    else if (bx == 84){ lvl = 3; tile = 0;       }
    else              { lvl = 4; tile = 0;       }

    const int stride = 8 << lvl;       // 8,16,32,64,128
    const int f      = 128 >> lvl;     // 128,64,32,16,8
    const int lg     = 7 - lvl;
    const int hw     = f * f;
    const int cellOff = (lvl >= 1 ? 16384 : 0) + (lvl >= 2 ? 4096 : 0)
                      + (lvl >= 3 ? 1024  : 0) + (lvl >= 4 ? 256  : 0);

    const int tid  = threadIdx.x;
    const int lane = tid & 31;
    const int wid  = tid >> 5;

    // ---- Warp 0: compact GT data for (img,lvl) into shared.
    // Inputs are 24 KB total -> L2-resident across replays (~250 cyc hits);
    // this overlaps with warps 1-7's zero-fill burst below.
    if (wid == 0) {
        const float ff  = (float)f;
        const float inv = 1.0f / (float)stride;   // exact (power of 2)
        int base = 0;
        #pragma unroll
        for (int half = 0; half < 2; ++half) {
            const int g = half * 32 + lane;
            const float* bp = g_boxes + ((size_t)img * MAXGT + g) * 5;
            float bx1 = bp[0], by1 = bp[1], bx2 = bp[2], by2 = bp[3];
            int   lab = (int)bp[4];
            bool  valid = (g_levels[img * MAXGT + g] == lvl);

            float px1 = bx1 * inv, py1 = by1 * inv;
            float px2 = bx2 * inv, py2 = by2 * inv;
            float w = px2 - px1, h = py2 - py1;

            int pp1x, pp1y, pp2x, pp2y;   // POS_SCALE=0.2 -> a=0.4
            int ii1x, ii1y, ii2x, ii2y;   // IGNORE_SCALE=0.5 -> a=0.25
            prop_bounds(px1, py1, px2, py2, w, h, 0.4f,  ff, pp1x, pp1y, pp2x, pp2y);
            prop_bounds(px1, py1, px2, py2, w, h, 0.25f, ff, ii1x, ii1y, ii2x, ii2y);

            unsigned bm = __ballot_sync(0xffffffffu, valid);
            int pos = base + __popc(bm & ((1u << lane) - 1u));
            if (valid) {
                s_pos[pos] = make_int4(pp1x, pp1y, pp2x, pp2y);
                s_ign[pos] = make_int4(ii1x, ii1y, ii2x, ii2y);
                s_uni[pos] = make_int4(min(pp1x, ii1x), min(pp1y, ii1y),
                                       max(pp2x, ii2x), max(pp2y, ii2y));
                s_box[pos] = make_float4(bx1, by1, bx2, by2);
                s_area[pos] = (bx2 - bx1) * (by2 - by1);
                s_lab[pos] = lab;
            }
            base += __popc(bm);
        }
        if (lane == 0) s_n = base;
    }

    // ---- All warps: front-loaded coalesced zero fill of cls_t (20 x STG.128
    // per warp). Warps 1-7 issue this while warp 0 compacts; warp 0 follows.
    const int cellW0 = tile * 256 + (wid << 5);
    const bool fillv = (cellW0 < hw);    // hw multiple of 32 -> warp-uniform
    if (fillv) {
        float4* basep = reinterpret_cast<float4*>(
            out + OFF_CLS_T + ((size_t)img * HWTOT + cellOff + cellW0) * NCLS);
        const float4 z = make_float4(0.0f, 0.0f, 0.0f, 0.0f);
        #pragma unroll
        for (int i = 0; i < 20; ++i)
            basep[i * 32 + lane] = z;
    }

    __syncthreads();
    const int n = s_n;

    // ---- Per-cell assignment.
    const int cell    = tile * 256 + tid;
    const bool active = (cell < hw);
    const size_t imgCell = (size_t)img * HWTOT + cellOff + cell;
    const int y = cell >> lg;
    const int x = cell & (f - 1);

    // Warp-uniform bounding range of this warp's 32 consecutive cells.
    const int ymin = cellW0 >> lg;
    const int ymax = (cellW0 + 31) >> lg;
    int xlo, xhi;
    if (ymin == ymax) { xlo = cellW0 & (f - 1); xhi = xlo + 31; }
    else              { xlo = 0;                xhi = f - 1;    }

    bool  anyp = false, anyi = false;
    float best = 1.0e10f;
    int   bidx = 0;

    for (int g = 0; g < n; ++g) {
        int4 uu = s_uni[g];   // LDS broadcast (warp-uniform address)
        // Warp-uniform skip: does (pos U ign) bbox intersect warp range?
        if (uu.x <= xhi && uu.z > xlo && uu.y <= ymax && uu.w > ymin) {
            int4 pp = s_pos[g];
            int4 ii = s_ign[g];
            bool inp = (x >= pp.x) & (x < pp.z) & (y >= pp.y) & (y < pp.w);
            bool ini = (x >= ii.x) & (x < ii.z) & (y >= ii.y) & (y < ii.w);
            anyi |= ini;
            float a = s_area[g];
            anyp |= inp;
            if (inp & (a < best)) { best = a; bidx = g; }  // strict < = first-index tie-break
        }
    }

    // num_pos: warp-aggregated exact integer count into device accumulator.
    unsigned pm = __ballot_sync(0xffffffffu, active && anyp);
    if (lane == 0 && pm)
        atomicAdd(&d_np[img], (float)__popc(pm));

    if (active) {
        out[OFF_CLS_M + imgCell] = (anyp || !anyi) ? 1.0f : 0.0f;
        out[OFF_REG_M + imgCell] = anyp ? 1.0f : 0.0f;

        float4 rv = make_float4(0.0f, 0.0f, 0.0f, 0.0f);
        if (anyp) {
            float4 cb = s_box[bidx];
            float sx = ((float)x + 0.5f) * (float)stride;  // exact
            float sy = ((float)y + 0.5f) * (float)stride;
            rv.x = (sx - cb.x) * 0.25f;
            rv.y = (sy - cb.y) * 0.25f;
            rv.z = (cb.z - sx) * 0.25f;
            rv.w = (cb.w - sy) * 0.25f;
        }
        reinterpret_cast<float4*>(out + OFF_REG_T)[imgCell] = rv;

        // one-hot scatter (ordered after this warp's zero fill by __syncthreads)
        if (anyp)
            out[OFF_CLS_T + imgCell * NCLS + s_lab[bidx]] = 1.0f;
    }

    // ---- Completion ticket: last block finalizes num_pos, resets scratch.
    __threadfence();
    if (tid == 0) s_tick = atomicAdd(&d_ticket, 1u);
    __syncthreads();
    if (s_tick == TOTBLK - 1) {
        __threadfence();
        if (tid < BATCH) {
            float v = atomicAdd(&d_np[tid], 0.0f);   // coherent read
            out[OFF_NP + tid] = v;
            d_np[tid] = 0.0f;                        // reset for next replay
        }
        if (tid == 0) d_ticket = 0;
    }
}

extern "C" void kernel_launch(void* const* d_in, const int* in_sizes, int n_in,
                              void* d_out, int out_size)
{
    const int*   levels = (const int*)  d_in[0];  // (16,64) int32
    const float* boxes  = (const float*)d_in[1];  // (16,64,5) float32
    float* out = (float*)d_out;

    dim3 grid(NBLK, BATCH);
    fsaf_all<<<grid, 256>>>(levels, boxes, out);
}

// round 6
// speedup vs baseline: 1.0887x; 1.0887x over previous
#include <cuda_runtime.h>
#include <cstdint>

#define BATCH 16
#define MAXGT 64
#define NCLS 80
#define HWTOT 21824
#define NBLK 86                   // blocks per image: 64+16+4+1+1
#define TOTBLK (NBLK * BATCH)     // 1376

// Output layout (floats), concatenated in reference return order.
#define OFF_CLS_T 0ULL
#define OFF_CLS_M ((size_t)BATCH * HWTOT * NCLS)            // 27,934,720
#define OFF_NP    (OFF_CLS_M + (size_t)BATCH * HWTOT)       // 28,283,904
#define OFF_REG_T (OFF_NP + BATCH)                          // 28,283,920
#define OFF_REG_M (OFF_REG_T + (size_t)BATCH * HWTOT * 4)   // 29,680,656

__device__ float    d_np[BATCH];     // zero-init; reset by finalizer each replay
__device__ unsigned d_ticket = 0;    // completion ticket; reset each replay

// Shrunken/clipped region bounds exactly like reference _prop_box.
// __f*_rn intrinsics forbid FMA contraction (floor/ceil boundary safety).
static __device__ __forceinline__ void prop_bounds(
    float px1, float py1, float px2, float py2, float w, float h,
    float a, float ff,
    int& ox1, int& oy1, int& ox2, int& oy2)
{
    float n1 = floorf(__fadd_rn(px1, __fmul_rn(a, w)));
    float m1 = floorf(__fadd_rn(py1, __fmul_rn(a, h)));
    float n2 = ceilf (__fsub_rn(px2, __fmul_rn(a, w)));
    float m2 = ceilf (__fsub_rn(py2, __fmul_rn(a, h)));
    n2 = fminf(fmaxf(fmaxf(n2, n1 + 1.0f), 0.0f), ff);
    m2 = fminf(fmaxf(fmaxf(m2, m1 + 1.0f), 0.0f), ff);
    n1 = fminf(fmaxf(n1, 0.0f), ff - 1.0f);
    m1 = fminf(fmaxf(m1, 0.0f), ff - 1.0f);
    ox1 = (int)n1; oy1 = (int)m1; ox2 = (int)n2; oy2 = (int)m2;
}

__global__ void __launch_bounds__(256)
fsaf_all(const int* __restrict__ g_levels,
         const float* __restrict__ g_boxes,
         float* __restrict__ out)
{
    // Shared GT table, SoA. Written REDUNDANTLY by every warp with byte-
    // identical values (same inputs -> same ballots -> same data), so no
    // block barrier is needed: each warp only depends on its own writes
    // (ordered by __syncwarp); concurrent same-value stores from other
    // warps are harmless.
    __shared__ int4   s_pos[MAXGT];
    __shared__ int4   s_ign[MAXGT];
    __shared__ int4   s_uni[MAXGT];
    __shared__ float4 s_box[MAXGT];
    __shared__ float  s_area[MAXGT];
    __shared__ int    s_lab[MAXGT];
    __shared__ unsigned s_tick;

    const int img = blockIdx.y;
    const int bx  = blockIdx.x;

    int lvl, tile;
    if      (bx < 64) { lvl = 0; tile = bx;      }
    else if (bx < 80) { lvl = 1; tile = bx - 64; }
    else if (bx < 84) { lvl = 2; tile = bx - 80; }
    else if (bx == 84){ lvl = 3; tile = 0;       }
    else              { lvl = 4; tile = 0;       }

    const int stride = 8 << lvl;       // 8,16,32,64,128
    const int f      = 128 >> lvl;     // 128,64,32,16,8
    const int lg     = 7 - lvl;
    const int hw     = f * f;
    const int cellOff = (lvl >= 1 ? 16384 : 0) + (lvl >= 2 ? 4096 : 0)
                      + (lvl >= 3 ? 1024  : 0) + (lvl >= 4 ? 256  : 0);

    const int tid  = threadIdx.x;
    const int lane = tid & 31;
    const int wid  = tid >> 5;

    const int cellW0 = tile * 256 + (wid << 5);
    const bool warpv = (cellW0 < hw);    // hw multiple of 32 -> warp-uniform

    if (warpv) {
        // ---- 1) Front-loaded coalesced zero fill of this warp's cls_t slab
        // (20 x STG.128). Stores drain while the compaction below runs.
        float4* basep = reinterpret_cast<float4*>(
            out + OFF_CLS_T + ((size_t)img * HWTOT + cellOff + cellW0) * NCLS);
        {
            const float4 z = make_float4(0.0f, 0.0f, 0.0f, 0.0f);
            #pragma unroll
            for (int i = 0; i < 20; ++i)
                basep[i * 32 + lane] = z;
        }

        // ---- 2) Per-warp compaction of GT data for (img,lvl) into shared.
        // Inputs are ~24 KB total -> L2-resident across replays.
        int n;
        {
            const float ff  = (float)f;
            const float inv = 1.0f / (float)stride;   // exact (power of 2)
            int base = 0;
            #pragma unroll
            for (int half = 0; half < 2; ++half) {
                const int g = half * 32 + lane;
                const float* bp = g_boxes + ((size_t)img * MAXGT + g) * 5;
                float bx1 = bp[0], by1 = bp[1], bx2 = bp[2], by2 = bp[3];
                int   lab = (int)bp[4];
                bool  valid = (g_levels[img * MAXGT + g] == lvl);

                float px1 = bx1 * inv, py1 = by1 * inv;
                float px2 = bx2 * inv, py2 = by2 * inv;
                float w = px2 - px1, h = py2 - py1;

                int pp1x, pp1y, pp2x, pp2y;   // POS_SCALE=0.2 -> a=0.4
                int ii1x, ii1y, ii2x, ii2y;   // IGNORE_SCALE=0.5 -> a=0.25
                prop_bounds(px1, py1, px2, py2, w, h, 0.4f,  ff, pp1x, pp1y, pp2x, pp2y);
                prop_bounds(px1, py1, px2, py2, w, h, 0.25f, ff, ii1x, ii1y, ii2x, ii2y);

                unsigned bm = __ballot_sync(0xffffffffu, valid);
                int pos = base + __popc(bm & ((1u << lane) - 1u));
                if (valid) {
                    s_pos[pos] = make_int4(pp1x, pp1y, pp2x, pp2y);
                    s_ign[pos] = make_int4(ii1x, ii1y, ii2x, ii2y);
                    s_uni[pos] = make_int4(min(pp1x, ii1x), min(pp1y, ii1y),
                                           max(pp2x, ii2x), max(pp2y, ii2y));
                    s_box[pos] = make_float4(bx1, by1, bx2, by2);
                    s_area[pos] = (bx2 - bx1) * (by2 - by1);
                    s_lab[pos] = lab;
                }
                base += __popc(bm);
            }
            n = base;
        }
        __syncwarp();   // this warp's table writes visible to this warp

        // ---- 3) Per-cell assignment.
        const int cell = tile * 256 + tid;   // < hw (hw multiple of 32)
        const size_t imgCell = (size_t)img * HWTOT + cellOff + cell;
        const int y = cell >> lg;
        const int x = cell & (f - 1);

        // Warp-uniform bounding range of this warp's 32 consecutive cells.
        const int ymin = cellW0 >> lg;
        const int ymax = (cellW0 + 31) >> lg;
        int xlo, xhi;
        if (ymin == ymax) { xlo = cellW0 & (f - 1); xhi = xlo + 31; }
        else              { xlo = 0;                xhi = f - 1;    }

        bool  anyp = false, anyi = false;
        float best = 1.0e10f;
        int   bidx = 0;

        for (int g = 0; g < n; ++g) {
            int4 uu = s_uni[g];   // LDS broadcast (warp-uniform address)
            // Warp-uniform skip: does (pos U ign) bbox intersect warp range?
            if (uu.x <= xhi && uu.z > xlo && uu.y <= ymax && uu.w > ymin) {
                int4 pp = s_pos[g];
                int4 ii = s_ign[g];
                bool inp = (x >= pp.x) & (x < pp.z) & (y >= pp.y) & (y < pp.w);
                bool ini = (x >= ii.x) & (x < ii.z) & (y >= ii.y) & (y < ii.w);
                anyi |= ini;
                float a = s_area[g];
                anyp |= inp;
                if (inp & (a < best)) { best = a; bidx = g; }  // strict < = first-index tie-break
            }
        }

        // ---- 4) Tail stores.
        // num_pos: warp-aggregated exact integer count into device accumulator.
        unsigned pm = __ballot_sync(0xffffffffu, anyp);
        if (lane == 0 && pm)
            atomicAdd(&d_np[img], (float)__popc(pm));

        out[OFF_CLS_M + imgCell] = (anyp || !anyi) ? 1.0f : 0.0f;
        out[OFF_REG_M + imgCell] = anyp ? 1.0f : 0.0f;

        float4 rv = make_float4(0.0f, 0.0f, 0.0f, 0.0f);
        if (anyp) {
            float4 cb = s_box[bidx];
            float sx = ((float)x + 0.5f) * (float)stride;  // exact
            float sy = ((float)y + 0.5f) * (float)stride;
            rv.x = (sx - cb.x) * 0.25f;
            rv.y = (sy - cb.y) * 0.25f;
            rv.z = (cb.z - sx) * 0.25f;
            rv.w = (cb.w - sy) * 0.25f;
        }
        reinterpret_cast<float4*>(out + OFF_REG_T)[imgCell] = rv;

        // One-hot scatter: same warp wrote these lines in step 1; the
        // __syncwarp above ordered the fill before this store.
        if (anyp)
            out[OFF_CLS_T + imgCell * NCLS + s_lab[bidx]] = 1.0f;
    }

    // ---- Completion ticket: order all warps' d_np adds before the ticket,
    // last block finalizes num_pos and resets scratch for the next replay.
    __syncthreads();
    __threadfence();
    if (tid == 0) s_tick = atomicAdd(&d_ticket, 1u);
    __syncthreads();
    if (s_tick == TOTBLK - 1) {
        __threadfence();
        if (tid < BATCH) {
            float v = atomicAdd(&d_np[tid], 0.0f);   // coherent read
            out[OFF_NP + tid] = v;
            d_np[tid] = 0.0f;                        // reset for next replay
        }
        if (tid == 0) d_ticket = 0;
    }
}

extern "C" void kernel_launch(void* const* d_in, const int* in_sizes, int n_in,
                              void* d_out, int out_size)
{
    const int*   levels = (const int*)  d_in[0];  // (16,64) int32
    const float* boxes  = (const float*)d_in[1];  // (16,64,5) float32
    float* out = (float*)d_out;

    dim3 grid(NBLK, BATCH);
    fsaf_all<<<grid, 256>>>(levels, boxes, out);
}

// round 7
// speedup vs baseline: 1.1479x; 1.0544x over previous
#include <cuda_runtime.h>
#include <cstdint>

#define BATCH 16
#define MAXGT 64
#define NCLS 80
#define HWTOT 21824
#define NBLK 86                   // blocks per image: 64+16+4+1+1
#define TOTBLK (NBLK * BATCH)     // 1376

// Output layout (floats), concatenated in reference return order.
#define OFF_CLS_T 0ULL
#define OFF_CLS_M ((size_t)BATCH * HWTOT * NCLS)            // 27,934,720
#define OFF_NP    (OFF_CLS_M + (size_t)BATCH * HWTOT)       // 28,283,904
#define OFF_REG_T (OFF_NP + BATCH)                          // 28,283,920
#define OFF_REG_M (OFF_REG_T + (size_t)BATCH * HWTOT * 4)   // 29,680,656

__device__ float    d_np[BATCH];     // zero-init; reset by finalizer each replay
__device__ unsigned d_ticket = 0;    // completion ticket; reset each replay

// Shrunken/clipped region bounds exactly like reference _prop_box.
// __f*_rn intrinsics forbid FMA contraction (floor/ceil boundary safety).
static __device__ __forceinline__ void prop_bounds(
    float px1, float py1, float px2, float py2, float w, float h,
    float a, float ff,
    int& ox1, int& oy1, int& ox2, int& oy2)
{
    float n1 = floorf(__fadd_rn(px1, __fmul_rn(a, w)));
    float m1 = floorf(__fadd_rn(py1, __fmul_rn(a, h)));
    float n2 = ceilf (__fsub_rn(px2, __fmul_rn(a, w)));
    float m2 = ceilf (__fsub_rn(py2, __fmul_rn(a, h)));
    n2 = fminf(fmaxf(fmaxf(n2, n1 + 1.0f), 0.0f), ff);
    m2 = fminf(fmaxf(fmaxf(m2, m1 + 1.0f), 0.0f), ff);
    n1 = fminf(fmaxf(n1, 0.0f), ff - 1.0f);
    m1 = fminf(fmaxf(m1, 0.0f), ff - 1.0f);
    ox1 = (int)n1; oy1 = (int)m1; ox2 = (int)n2; oy2 = (int)m2;
}

__global__ void __launch_bounds__(256, 8)
fsaf_all(const int* __restrict__ g_levels,
         const float* __restrict__ g_boxes,
         float* __restrict__ out)
{
    // Shared GT table, SoA. Written REDUNDANTLY by every warp with byte-
    // identical values (same inputs -> same ballots -> same data), so no
    // block barrier is needed: each warp depends only on its own writes
    // (ordered by __syncwarp); concurrent same-value stores are harmless.
    __shared__ int4   s_pos[MAXGT];
    __shared__ int4   s_ign[MAXGT];
    __shared__ int4   s_uni[MAXGT];
    __shared__ float4 s_box[MAXGT];
    __shared__ float  s_area[MAXGT];
    __shared__ int    s_lab[MAXGT];
    __shared__ unsigned s_tick;

    const int img = blockIdx.y;
    const int bx  = blockIdx.x;

    int lvl, tile;
    if      (bx < 64) { lvl = 0; tile = bx;      }
    else if (bx < 80) { lvl = 1; tile = bx - 64; }
    else if (bx < 84) { lvl = 2; tile = bx - 80; }
    else if (bx == 84){ lvl = 3; tile = 0;       }
    else              { lvl = 4; tile = 0;       }

    const int stride = 8 << lvl;       // 8,16,32,64,128
    const int f      = 128 >> lvl;     // 128,64,32,16,8
    const int lg     = 7 - lvl;
    const int hw     = f * f;
    const int cellOff = (lvl >= 1 ? 16384 : 0) + (lvl >= 2 ? 4096 : 0)
                      + (lvl >= 3 ? 1024  : 0) + (lvl >= 4 ? 256  : 0);

    const int tid  = threadIdx.x;
    const int lane = tid & 31;
    const int wid  = tid >> 5;

    const int cellW0 = tile * 256 + (wid << 5);
    const bool warpv = (cellW0 < hw);    // hw multiple of 32 -> warp-uniform

    if (warpv) {
        // ---- 1) Issue ALL compaction input loads first (12 LDG.32 per
        // thread, L2-resident inputs). They drain under the fill burst.
        int   lv[2];
        float bb[2][5];
        #pragma unroll
        for (int half = 0; half < 2; ++half) {
            const int g = half * 32 + lane;
            lv[half] = g_levels[img * MAXGT + g];
            const float* bp = g_boxes + ((size_t)img * MAXGT + g) * 5;
            #pragma unroll
            for (int j = 0; j < 5; ++j) bb[half][j] = bp[j];
        }

        // ---- 2) Front-loaded coalesced zero fill of this warp's cls_t slab
        // (20 x STG.128).
        float4* basep = reinterpret_cast<float4*>(
            out + OFF_CLS_T + ((size_t)img * HWTOT + cellOff + cellW0) * NCLS);
        {
            const float4 z = make_float4(0.0f, 0.0f, 0.0f, 0.0f);
            #pragma unroll
            for (int i = 0; i < 20; ++i)
                basep[i * 32 + lane] = z;
        }

        // ---- 3) Per-warp compaction of GT data for (img,lvl) into shared.
        int n;
        {
            const float ff  = (float)f;
            const float inv = 1.0f / (float)stride;   // exact (power of 2)
            int base = 0;
            #pragma unroll
            for (int half = 0; half < 2; ++half) {
                float bx1 = bb[half][0], by1 = bb[half][1];
                float bx2 = bb[half][2], by2 = bb[half][3];
                int   lab = (int)bb[half][4];
                bool  valid = (lv[half] == lvl);

                float px1 = bx1 * inv, py1 = by1 * inv;
                float px2 = bx2 * inv, py2 = by2 * inv;
                float w = px2 - px1, h = py2 - py1;

                int pp1x, pp1y, pp2x, pp2y;   // POS_SCALE=0.2 -> a=0.4
                int ii1x, ii1y, ii2x, ii2y;   // IGNORE_SCALE=0.5 -> a=0.25
                prop_bounds(px1, py1, px2, py2, w, h, 0.4f,  ff, pp1x, pp1y, pp2x, pp2y);
                prop_bounds(px1, py1, px2, py2, w, h, 0.25f, ff, ii1x, ii1y, ii2x, ii2y);

                unsigned bm = __ballot_sync(0xffffffffu, valid);
                int pos = base + __popc(bm & ((1u << lane) - 1u));
                if (valid) {
                    s_pos[pos] = make_int4(pp1x, pp1y, pp2x, pp2y);
                    s_ign[pos] = make_int4(ii1x, ii1y, ii2x, ii2y);
                    s_uni[pos] = make_int4(min(pp1x, ii1x), min(pp1y, ii1y),
                                           max(pp2x, ii2x), max(pp2y, ii2y));
                    s_box[pos] = make_float4(bx1, by1, bx2, by2);
                    s_area[pos] = (bx2 - bx1) * (by2 - by1);
                    s_lab[pos] = lab;
                }
                base += __popc(bm);
            }
            n = base;
        }
        __syncwarp();   // this warp's table writes visible to this warp

        // ---- 4) Per-cell assignment.
        const int cell = tile * 256 + tid;   // < hw (hw multiple of 32)
        const size_t imgCell = (size_t)img * HWTOT + cellOff + cell;
        const int y = cell >> lg;
        const int x = cell & (f - 1);

        // Warp-uniform bounding range of this warp's 32 consecutive cells.
        const int ymin = cellW0 >> lg;
        const int ymax = (cellW0 + 31) >> lg;
        int xlo, xhi;
        if (ymin == ymax) { xlo = cellW0 & (f - 1); xhi = xlo + 31; }
        else              { xlo = 0;                xhi = f - 1;    }

        bool  anyp = false, anyi = false;
        float best = 1.0e10f;
        int   bidx = 0;

        for (int g = 0; g < n; ++g) {
            int4 uu = s_uni[g];   // LDS broadcast (warp-uniform address)
            // Warp-uniform skip: does (pos U ign) bbox intersect warp range?
            if (uu.x <= xhi && uu.z > xlo && uu.y <= ymax && uu.w > ymin) {
                int4 pp = s_pos[g];
                int4 ii = s_ign[g];
                bool inp = (x >= pp.x) & (x < pp.z) & (y >= pp.y) & (y < pp.w);
                bool ini = (x >= ii.x) & (x < ii.z) & (y >= ii.y) & (y < ii.w);
                anyi |= ini;
                float a = s_area[g];
                anyp |= inp;
                if (inp & (a < best)) { best = a; bidx = g; }  // strict < = first-index tie-break
            }
        }

        // ---- 5) Tail stores.
        // num_pos: warp-aggregated exact integer count into device accumulator.
        unsigned pm = __ballot_sync(0xffffffffu, anyp);
        if (lane == 0 && pm)
            atomicAdd(&d_np[img], (float)__popc(pm));

        out[OFF_CLS_M + imgCell] = (anyp || !anyi) ? 1.0f : 0.0f;
        out[OFF_REG_M + imgCell] = anyp ? 1.0f : 0.0f;

        float4 rv = make_float4(0.0f, 0.0f, 0.0f, 0.0f);
        if (anyp) {
            float4 cb = s_box[bidx];
            float sx = ((float)x + 0.5f) * (float)stride;  // exact
            float sy = ((float)y + 0.5f) * (float)stride;
            rv.x = (sx - cb.x) * 0.25f;
            rv.y = (sy - cb.y) * 0.25f;
            rv.z = (cb.z - sx) * 0.25f;
            rv.w = (cb.w - sy) * 0.25f;
        }
        reinterpret_cast<float4*>(out + OFF_REG_T)[imgCell] = rv;

        // One-hot scatter: same warp wrote these lines in step 2; the
        // __syncwarp above ordered the fill before this store.
        if (anyp)
            out[OFF_CLS_T + imgCell * NCLS + s_lab[bidx]] = 1.0f;
    }

    // ---- Completion ticket: order all warps' d_np adds before the ticket,
    // last block finalizes num_pos and resets scratch for the next replay.
    __syncthreads();
    __threadfence();
    if (tid == 0) s_tick = atomicAdd(&d_ticket, 1u);
    __syncthreads();
    if (s_tick == TOTBLK - 1) {
        __threadfence();
        if (tid < BATCH) {
            float v = atomicAdd(&d_np[tid], 0.0f);   // coherent read
            out[OFF_NP + tid] = v;
            d_np[tid] = 0.0f;                        // reset for next replay
        }
        if (tid == 0) d_ticket = 0;
    }
}

extern "C" void kernel_launch(void* const* d_in, const int* in_sizes, int n_in,
                              void* d_out, int out_size)
{
    const int*   levels = (const int*)  d_in[0];  // (16,64) int32
    const float* boxes  = (const float*)d_in[1];  // (16,64,5) float32
    float* out = (float*)d_out;

    dim3 grid(NBLK, BATCH);
    fsaf_all<<<grid, 256>>>(levels, boxes, out);
}